// round 12
// baseline (speedup 1.0000x reference)
#include <cuda_runtime.h>

// Problem constants (fixed shapes)
#define DX 256
#define DY 256
#define DZ 32
#define DT 5
#define CIN 8
#define COUT 8
#define NVOX 10485760            // DT*DZ*DY*DX
#define MASK_QWORDS 163840       // NVOX / 64
#define LIST_CAP 131072

// Scratch: __device__ globals (no allocation allowed)
__device__ unsigned long long g_mask64[MASK_QWORDS];
__device__ unsigned g_list[LIST_CAP];
__device__ unsigned g_count;
__device__ float    g_wsum[81 * 8];

// ---------------------------------------------------------------------------
// K0: clear bitmask + counter, precompute Wsum[k][f] = sum_c W[k][c][f]
// ---------------------------------------------------------------------------
__global__ void k_init(const float* __restrict__ W) {
    int i = blockIdx.x * blockDim.x + threadIdx.x;
    if (i < MASK_QWORDS) g_mask64[i] = 0ull;
    if (i == 0) g_count = 0u;
    if (i < 81 * 8) {
        int k = i >> 3, f = i & 7;
        float s = 0.f;
#pragma unroll
        for (int c = 0; c < CIN; ++c) s += W[k * (CIN * COUT) + c * COUT + f];
        g_wsum[i] = s;
    }
}

// ---------------------------------------------------------------------------
// K1: quantize points -> voxel ids, set occupancy bit, append unique vids
// Bit-match XLA: /0.2f is folded to *5.0f (reciprocal rounds exactly).
// ---------------------------------------------------------------------------
__global__ void k_points(const float4* __restrict__ pts, int n) {
    int i = blockIdx.x * blockDim.x + threadIdx.x;
    if (i >= n) return;
    float4 p = pts[i];
    int ix = (int)floorf(__fmul_rn(__fadd_rn(p.x, 25.6f), 5.0f));
    int iy = (int)floorf(__fmul_rn(__fadd_rn(p.y, 25.6f), 5.0f));
    int iz = (int)floorf(__fmul_rn(__fadd_rn(p.z, 3.2f),  5.0f));
    int it = (int)floorf(p.w);
    ix = min(max(ix, 0), DX - 1);
    iy = min(max(iy, 0), DY - 1);
    iz = min(max(iz, 0), DZ - 1);
    it = min(max(it, 0), DT - 1);
    unsigned vid = (((unsigned)it * DZ + (unsigned)iz) * DY + (unsigned)iy) * DX + (unsigned)ix;
    unsigned* mask32 = (unsigned*)g_mask64;
    unsigned bit = 1u << (vid & 31u);
    unsigned old = atomicOr(&mask32[vid >> 5], bit);
    if (!(old & bit)) {
        unsigned pos = atomicAdd(&g_count, 1u);
        if (pos < LIST_CAP) g_list[pos] = vid;
    }
}

// ---------------------------------------------------------------------------
// K2: zero-fill dense output (335.5 MB), grid-stride 128-bit stores
// ---------------------------------------------------------------------------
__global__ void k_zero(uint4* __restrict__ out, int n4) {
    int stride = gridDim.x * blockDim.x;
    for (int i = blockIdx.x * blockDim.x + threadIdx.x; i < n4; i += stride)
        out[i] = make_uint4(0u, 0u, 0u, 0u);
}

// ---------------------------------------------------------------------------
// K3: one thread per active voxel. All 27 row loads issued as ONE independent
// batch (MLP=27). bpos = x & 63 is uniform across rows (all offsets are
// multiples of 64), so straddle handling is a per-thread branch.
// k index layout: k = (dx+1)*27 + r, r = (dy+1)*9 + (dz+1)*3 + (dt+1).
// ---------------------------------------------------------------------------
__device__ __forceinline__ void acc_add(const float4* __restrict__ s, int k,
                                        float4& a0, float4& a1) {
    float4 a = s[k * 2], b = s[k * 2 + 1];
    a0.x += a.x; a0.y += a.y; a0.z += a.z; a0.w += a.w;
    a1.x += b.x; a1.y += b.y; a1.z += b.z; a1.w += b.w;
}

__device__ __forceinline__ void acc_m(unsigned m, int r, const float4* __restrict__ s,
                                      float4& a0, float4& a1) {
    if (m & 1u) acc_add(s, r, a0, a1);        // dx = -1
    if (m & 2u) acc_add(s, 27 + r, a0, a1);   // dx =  0
    if (m & 4u) acc_add(s, 54 + r, a0, a1);   // dx = +1
}

__global__ __launch_bounds__(256) void k_conv(float* __restrict__ out) {
    __shared__ float4 s_wsum4[81 * 2];
    for (int i = threadIdx.x; i < 81 * 2; i += blockDim.x)
        s_wsum4[i] = ((const float4*)g_wsum)[i];
    __syncthreads();

    int vi = blockIdx.x * blockDim.x + threadIdx.x;
    unsigned cnt = g_count;
    if (cnt > LIST_CAP) cnt = LIST_CAP;
    if ((unsigned)vi >= cnt) return;

    unsigned vid = g_list[vi];
    int x = vid & 255;
    int y = (vid >> 8) & 255;
    int z = (vid >> 16) & 31;
    int t = vid >> 21;

    // Batched phase: 27 independent LDG.64 (invalid rows read word 0, masked later)
    unsigned long long w[27];
    unsigned valid = 0u;
#pragma unroll
    for (int r = 0; r < 27; ++r) {
        const int dy = r / 9 - 1;
        const int dz = (r / 3) % 3 - 1;
        const int dt = r % 3 - 1;
        bool v = ((unsigned)(y + dy) < (unsigned)DY) &
                 ((unsigned)(z + dz) < (unsigned)DZ) &
                 ((unsigned)(t + dt) < (unsigned)DT);
        int base = (int)vid + dy * DX + dz * (DY * DX) + dt * (DZ * DY * DX);
        unsigned wi = v ? ((unsigned)base >> 6) : 0u;
        w[r] = g_mask64[wi];
        valid |= (v ? 1u : 0u) << r;
    }

    unsigned xmask = 7u;
    if (x == 0)      xmask &= ~1u;   // dx=-1 out of bounds
    if (x == DX - 1) xmask &= ~4u;   // dx=+1 out of bounds

    float4 acc0 = make_float4(0.f, 0.f, 0.f, 0.f);
    float4 acc1 = make_float4(0.f, 0.f, 0.f, 0.f);

    unsigned bpos = (unsigned)x & 63u;
    if (bpos >= 1u && bpos <= 62u) {             // ~97% of threads
#pragma unroll
        for (int r = 0; r < 27; ++r) {
            unsigned m = (unsigned)((w[r] >> (bpos - 1u)) & 7ull);
            m = ((valid >> r) & 1u) ? (m & xmask) : 0u;
            acc_m(m, r, s_wsum4, acc0, acc1);
        }
    } else if (bpos == 0u) {                     // x in {0,64,128,192}
        int d = (x == 0) ? 0 : -1;               // bit0 masked by xmask when x==0
#pragma unroll
        for (int r = 0; r < 27; ++r) {
            const int dy = r / 9 - 1;
            const int dz = (r / 3) % 3 - 1;
            const int dt = r % 3 - 1;
            int base = (int)vid + dy * DX + dz * (DY * DX) + dt * (DZ * DY * DX);
            bool v = (valid >> r) & 1u;
            unsigned wi = v ? ((unsigned)base >> 6) : 1u;
            unsigned long long lo = g_mask64[(int)wi + d];
            unsigned m = (unsigned)((lo >> 63) | ((w[r] & 3ull) << 1));
            m = v ? (m & xmask) : 0u;
            acc_m(m, r, s_wsum4, acc0, acc1);
        }
    } else {                                     // bpos == 63, x in {63,127,191,255}
        int d = (x == DX - 1) ? 0 : 1;           // bit2 masked by xmask when x==255
#pragma unroll
        for (int r = 0; r < 27; ++r) {
            const int dy = r / 9 - 1;
            const int dz = (r / 3) % 3 - 1;
            const int dt = r % 3 - 1;
            int base = (int)vid + dy * DX + dz * (DY * DX) + dt * (DZ * DY * DX);
            bool v = (valid >> r) & 1u;
            unsigned wi = v ? ((unsigned)base >> 6) : 0u;
            unsigned long long hi = g_mask64[(int)wi + d];
            unsigned m = (unsigned)(((w[r] >> 62) & 3ull) | ((hi & 1ull) << 2));
            m = v ? (m & xmask) : 0u;
            acc_m(m, r, s_wsum4, acc0, acc1);
        }
    }

    out[0u * NVOX + vid] = fmaxf(acc0.x, 0.f);
    out[1u * NVOX + vid] = fmaxf(acc0.y, 0.f);
    out[2u * NVOX + vid] = fmaxf(acc0.z, 0.f);
    out[3u * NVOX + vid] = fmaxf(acc0.w, 0.f);
    out[4u * NVOX + vid] = fmaxf(acc1.x, 0.f);
    out[5u * NVOX + vid] = fmaxf(acc1.y, 0.f);
    out[6u * NVOX + vid] = fmaxf(acc1.z, 0.f);
    out[7u * NVOX + vid] = fmaxf(acc1.w, 0.f);
}

// ---------------------------------------------------------------------------
extern "C" void kernel_launch(void* const* d_in, const int* in_sizes, int n_in,
                              void* d_out, int out_size) {
    const float4* pts = (const float4*)d_in[0];
    const float*  W   = (const float*)d_in[1];
    float* out = (float*)d_out;
    int n = in_sizes[0] / 4;

    int n4 = out_size / 4;                       // 20.97M uint4
    k_zero<<<148 * 8, 256>>>((uint4*)d_out, n4); // grid-stride, full-chip

    k_init<<<(MASK_QWORDS + 255) / 256, 256>>>(W);
    k_points<<<(n + 255) / 256, 256>>>(pts, n);

    k_conv<<<(n + 255) / 256, 256>>>(out);       // n threads >= active voxel count
}

// round 14
// speedup vs baseline: 1.1359x; 1.1359x over previous
#include <cuda_runtime.h>

// Problem constants (fixed shapes)
#define DX 256
#define DY 256
#define DZ 32
#define DT 5
#define CIN 8
#define COUT 8
#define NVOX 10485760            // DT*DZ*DY*DX
#define MASK_QWORDS 163840       // NVOX / 64  (one u64 word per 64 x-consecutive voxels)

// Scratch: __device__ globals (no allocation allowed)
__device__ unsigned long long g_mask64[MASK_QWORDS];
__device__ float g_lut[27 * 8 * 8];   // [r][m3][f]: pre-summed Wsum over x-bit pattern

// Word offset of row r = (dy+1)*9+(dz+1)*3+(dt+1), in 64-voxel words
__device__ __forceinline__ int row_off_words(int r) {
    int dy = r / 9 - 1, dz = (r / 3) % 3 - 1, dt = r % 3 - 1;
    return dy * 4 + dz * 1024 + dt * 32768;
}

// ---------------------------------------------------------------------------
// K0: clear bitmask; build LUT[r][m][f] = sum over set dx-bits of
//     Wsum[dx*27+r][f], Wsum[k][f] = sum_c W[k][c][f].
//     Original kernel index: k = (dx+1)*27 + (dy+1)*9 + (dz+1)*3 + (dt+1).
// ---------------------------------------------------------------------------
__global__ void k_init(const float* __restrict__ W) {
    int i = blockIdx.x * blockDim.x + threadIdx.x;
    if (i < MASK_QWORDS) g_mask64[i] = 0ull;
    if (i < 27 * 8 * 8) {
        int r = i >> 6, m = (i >> 3) & 7, f = i & 7;
        float s = 0.f;
#pragma unroll
        for (int dxb = 0; dxb < 3; ++dxb) {
            if ((m >> dxb) & 1) {
                int k = dxb * 27 + r;
#pragma unroll
                for (int c = 0; c < CIN; ++c) s += W[k * (CIN * COUT) + c * COUT + f];
            }
        }
        g_lut[i] = s;   // layout: ((r*8+m)*8 + f) == i
    }
}

// ---------------------------------------------------------------------------
// K1: quantize points -> voxel ids, set occupancy bit (no list needed).
// Bit-match XLA: /0.2f is folded to *5.0f (reciprocal rounds exactly).
// ---------------------------------------------------------------------------
__global__ void k_points(const float4* __restrict__ pts, int n) {
    int i = blockIdx.x * blockDim.x + threadIdx.x;
    if (i >= n) return;
    float4 p = pts[i];
    int ix = (int)floorf(__fmul_rn(__fadd_rn(p.x, 25.6f), 5.0f));
    int iy = (int)floorf(__fmul_rn(__fadd_rn(p.y, 25.6f), 5.0f));
    int iz = (int)floorf(__fmul_rn(__fadd_rn(p.z, 3.2f),  5.0f));
    int it = (int)floorf(p.w);
    ix = min(max(ix, 0), DX - 1);
    iy = min(max(iy, 0), DY - 1);
    iz = min(max(iz, 0), DZ - 1);
    it = min(max(it, 0), DT - 1);
    unsigned vid = (((unsigned)it * DZ + (unsigned)iz) * DY + (unsigned)iy) * DX + (unsigned)ix;
    atomicOr((unsigned*)g_mask64 + (vid >> 5), 1u << (vid & 31u));
}

// ---------------------------------------------------------------------------
// K2: zero-fill dense output (335.5 MB), grid-stride 128-bit stores
// ---------------------------------------------------------------------------
__global__ void k_zero(uint4* __restrict__ out, int n4) {
    int stride = gridDim.x * blockDim.x;
    for (int i = blockIdx.x * blockDim.x + threadIdx.x; i < n4; i += stride)
        out[i] = make_uint4(0u, 0u, 0u, 0u);
}

// ---------------------------------------------------------------------------
// K3: dense word-scan. One thread per 64-voxel mask word; 27 row loads are
// COALESCED (consecutive lanes -> consecutive words). For each set bit of the
// center word, accumulate via LUT (avg ~1.8 nonzero rows/bit at 1% density).
// x-straddle (bit 0/63, ~3% of bits) takes a rare direct-load path.
// ---------------------------------------------------------------------------
__device__ __forceinline__ void lut_add(const float4* __restrict__ s, int r, unsigned m,
                                        float4& a0, float4& a1) {
    const float4* p = s + (r * 8 + (int)m) * 2;
    float4 a = p[0], b = p[1];
    a0.x += a.x; a0.y += a.y; a0.z += a.z; a0.w += a.w;
    a1.x += b.x; a1.y += b.y; a1.z += b.z; a1.w += b.w;
}

__global__ __launch_bounds__(256) void k_conv(float* __restrict__ out) {
    __shared__ float4 s_lut[27 * 8 * 2];
    for (int i = threadIdx.x; i < 27 * 8 * 2; i += 256)
        s_lut[i] = ((const float4*)g_lut)[i];
    __syncthreads();

    int wi = blockIdx.x * 256 + threadIdx.x;   // grid exactly covers MASK_QWORDS
    int y = (wi >> 2) & 255;
    int z = (wi >> 10) & 31;
    int t = wi >> 15;
    int q = wi & 3;                            // x-quarter within the 256-wide row

    // Coalesced batch: 27 row words (invalid rows -> 0)
    unsigned long long w[27];
    unsigned validm = 0u;
#pragma unroll
    for (int r = 0; r < 27; ++r) {
        const int dy = r / 9 - 1, dz = (r / 3) % 3 - 1, dt = r % 3 - 1;
        bool v = ((unsigned)(y + dy) < (unsigned)DY) &
                 ((unsigned)(z + dz) < (unsigned)DZ) &
                 ((unsigned)(t + dt) < (unsigned)DT);
        int wr = wi + dy * 4 + dz * 1024 + dt * 32768;
        w[r] = v ? g_mask64[wr] : 0ull;
        validm |= (v ? 1u : 0u) << r;
    }

    unsigned long long bits = w[13];           // center row (dy=dz=dt=0)
    while (bits) {
        int b = __ffsll((long long)bits) - 1;
        bits &= bits - 1ull;

        float4 acc0 = make_float4(0.f, 0.f, 0.f, 0.f);
        float4 acc1 = make_float4(0.f, 0.f, 0.f, 0.f);

        if (b >= 1 && b <= 62) {               // common path
#pragma unroll
            for (int r = 0; r < 27; ++r) {
                unsigned m = (unsigned)((w[r] >> (b - 1)) & 7ull);
                if (m) lut_add(s_lut, r, m, acc0, acc1);
            }
        } else if (b == 0) {                   // x = 64q: left bit from word wi-1
            unsigned mlo = 0u;
            if (q != 0) {
#pragma unroll
                for (int r = 0; r < 27; ++r)
                    if ((validm >> r) & 1u)
                        mlo |= (unsigned)((g_mask64[wi + row_off_words(r) - 1] >> 63) & 1ull) << r;
            }
#pragma unroll
            for (int r = 0; r < 27; ++r) {
                unsigned m = ((mlo >> r) & 1u) | ((unsigned)(w[r] & 3ull) << 1);
                if (m) lut_add(s_lut, r, m, acc0, acc1);
            }
        } else {                               // b == 63: right bit from word wi+1
            unsigned mhi = 0u;
            if (q != 3) {
#pragma unroll
                for (int r = 0; r < 27; ++r)
                    if ((validm >> r) & 1u)
                        mhi |= (unsigned)(g_mask64[wi + row_off_words(r) + 1] & 1ull) << r;
            }
#pragma unroll
            for (int r = 0; r < 27; ++r) {
                unsigned m = (unsigned)((w[r] >> 62) & 3ull) | (((mhi >> r) & 1u) << 2);
                if (m) lut_add(s_lut, r, m, acc0, acc1);
            }
        }

        unsigned vid = ((unsigned)wi << 6) | (unsigned)b;
        out[0u * NVOX + vid] = fmaxf(acc0.x, 0.f);
        out[1u * NVOX + vid] = fmaxf(acc0.y, 0.f);
        out[2u * NVOX + vid] = fmaxf(acc0.z, 0.f);
        out[3u * NVOX + vid] = fmaxf(acc0.w, 0.f);
        out[4u * NVOX + vid] = fmaxf(acc1.x, 0.f);
        out[5u * NVOX + vid] = fmaxf(acc1.y, 0.f);
        out[6u * NVOX + vid] = fmaxf(acc1.z, 0.f);
        out[7u * NVOX + vid] = fmaxf(acc1.w, 0.f);
    }
}

// ---------------------------------------------------------------------------
extern "C" void kernel_launch(void* const* d_in, const int* in_sizes, int n_in,
                              void* d_out, int out_size) {
    const float4* pts = (const float4*)d_in[0];
    const float*  W   = (const float*)d_in[1];
    float* out = (float*)d_out;
    int n = in_sizes[0] / 4;

    int n4 = out_size / 4;                       // 20.97M uint4
    k_zero<<<148 * 8, 256>>>((uint4*)d_out, n4); // grid-stride, full-chip

    k_init<<<MASK_QWORDS / 256, 256>>>(W);
    k_points<<<(n + 255) / 256, 256>>>(pts, n);

    k_conv<<<MASK_QWORDS / 256, 256>>>(out);     // one thread per mask word
}